// round 2
// baseline (speedup 1.0000x reference)
#include <cuda_runtime.h>

#define TT 512
#define BB 32
#define HH 512
#define G4 2048

// ---- scratch (device globals: no allocation allowed) ----
__device__ float g_xproj[2][TT * BB][G4];      // 256 MB: precomputed x@Wih^T + bias
__device__ float g_h[2][2][HH][BB];            // [phase][dir][k][b] double-buffered h
__device__ unsigned int g_bar[2];              // per-direction barrier counters

// ---- packed fp32x2 helpers (sm_103a FFMA2) ----
static __device__ __forceinline__ unsigned long long pk2(float x, float y) {
    unsigned long long r;
    asm("mov.b64 %0, {%1, %2};" : "=l"(r) : "f"(x), "f"(y));
    return r;
}
static __device__ __forceinline__ void upk2(unsigned long long v, float& x, float& y) {
    asm("mov.b64 {%0, %1}, %2;" : "=f"(x), "=f"(y) : "l"(v));
}
static __device__ __forceinline__ unsigned long long fma2(unsigned long long a,
                                                          unsigned long long b,
                                                          unsigned long long c) {
    unsigned long long d;
    asm("fma.rn.f32x2 %0, %1, %2, %3;" : "=l"(d) : "l"(a), "l"(b), "l"(c));
    return d;
}

// ================= 1) embedding gather =================
__global__ void embed_kernel(const int* __restrict__ seq,
                             const float* __restrict__ emb,
                             float* __restrict__ out_emb) {
    int row = blockIdx.x;                       // t*B + b
    int s = seq[row];
    const float4* src = (const float4*)(emb + (size_t)s * HH);
    float4* dst = (float4*)(out_emb + (size_t)row * HH);
    dst[threadIdx.x] = src[threadIdx.x];        // 128 thr * float4 = 512 floats
}

// ================= 2) input projection GEMM (both dirs) =================
// C[d][m][j] = sum_k emb[m][k] * Wih_d[j][k] + (bih_d[j]+bhh_d[j])
__global__ __launch_bounds__(256) void xproj_kernel(
    const float* __restrict__ A,
    const float* __restrict__ Wf, const float* __restrict__ Wb,
    const float* __restrict__ b1f, const float* __restrict__ b2f,
    const float* __restrict__ b1b, const float* __restrict__ b2b) {
    const int d = blockIdx.z;
    const float* __restrict__ W  = d ? Wb : Wf;
    const float* __restrict__ bi = d ? b1b : b1f;
    const float* __restrict__ bh = d ? b2b : b2f;
    float* C = &g_xproj[d][0][0];

    __shared__ float Asm[8][128];
    __shared__ float Bsm[8][128];

    int tid = threadIdx.x;
    int tx = tid & 15, ty = tid >> 4;
    int m0 = blockIdx.y * 128, n0 = blockIdx.x * 128;
    int lr = tid >> 1, lk = (tid & 1) * 4;
    const float* Aptr = A + (size_t)(m0 + lr) * HH + lk;
    const float* Wptr = W + (size_t)(n0 + lr) * HH + lk;

    unsigned long long acc[8][4];
#pragma unroll
    for (int i = 0; i < 8; i++)
#pragma unroll
        for (int j = 0; j < 4; j++) acc[i][j] = pk2(0.f, 0.f);

    for (int k0 = 0; k0 < HH; k0 += 8) {
        float4 av = *(const float4*)(Aptr + k0);
        float4 bv = *(const float4*)(Wptr + k0);
        Asm[lk + 0][lr] = av.x; Asm[lk + 1][lr] = av.y;
        Asm[lk + 2][lr] = av.z; Asm[lk + 3][lr] = av.w;
        Bsm[lk + 0][lr] = bv.x; Bsm[lk + 1][lr] = bv.y;
        Bsm[lk + 2][lr] = bv.z; Bsm[lk + 3][lr] = bv.w;
        __syncthreads();
#pragma unroll
        for (int kk = 0; kk < 8; kk++) {
            float4 a0 = *(const float4*)&Asm[kk][ty * 8];
            float4 a1 = *(const float4*)&Asm[kk][ty * 8 + 4];
            float4 c0 = *(const float4*)&Bsm[kk][tx * 8];
            float4 c1 = *(const float4*)&Bsm[kk][tx * 8 + 4];
            unsigned long long bp[4] = {pk2(c0.x, c0.y), pk2(c0.z, c0.w),
                                        pk2(c1.x, c1.y), pk2(c1.z, c1.w)};
            float aa[8] = {a0.x, a0.y, a0.z, a0.w, a1.x, a1.y, a1.z, a1.w};
#pragma unroll
            for (int i = 0; i < 8; i++) {
                unsigned long long as = pk2(aa[i], aa[i]);
#pragma unroll
                for (int j = 0; j < 4; j++) acc[i][j] = fma2(as, bp[j], acc[i][j]);
            }
        }
        __syncthreads();
    }

    float bias[8];
#pragma unroll
    for (int j = 0; j < 8; j++) {
        int n = n0 + tx * 8 + j;
        bias[j] = bi[n] + bh[n];
    }
#pragma unroll
    for (int i = 0; i < 8; i++) {
        float v[8];
#pragma unroll
        for (int j = 0; j < 4; j++) upk2(acc[i][j], v[2 * j], v[2 * j + 1]);
        size_t base = (size_t)(m0 + ty * 8 + i) * G4 + n0 + tx * 8;
        float4 o0 = make_float4(v[0] + bias[0], v[1] + bias[1], v[2] + bias[2], v[3] + bias[3]);
        float4 o1 = make_float4(v[4] + bias[4], v[5] + bias[5], v[6] + bias[6], v[7] + bias[7]);
        *(float4*)(C + base) = o0;
        *(float4*)(C + base + 4) = o1;
    }
}

// ================= 3) persistent recurrent kernel =================
// 128 blocks: dir = blk>>6, gb = blk&63 owns h indices [gb*8, gb*8+8)
// -> gate rows {q*512 + gb*8 + r : q in 0..3, r in 0..7}
__global__ __launch_bounds__(256) void lstm_kernel(
    const float* __restrict__ Whh_f, const float* __restrict__ Whh_b,
    const int* __restrict__ lens,
    float* __restrict__ out0,        // outputs [T,B,2,H]
    float* __restrict__ out1) {      // hidden  [2,T,B,H]
    extern __shared__ float sm[];
    float* wsm  = sm;                  // [512][32]  (k-major weight slice)
    float* hsm  = wsm + HH * 32;       // [512][36]  (h, padded stride 36)
    float* gsm  = hsm + HH * 36;       // [32][33]   (gate staging)
    float* csm  = gsm + 32 * 33;       // [8][33]    (cell state, persistent)
    float* hbuf = csm + 8 * 33;        // [8][33]    (output staging)
    int*   lsm  = (int*)(hbuf + 8 * 33);  // [32]

    int tid = threadIdx.x;
    int d  = blockIdx.x >> 6;
    int gb = blockIdx.x & 63;
    const float* __restrict__ Whh = d ? Whh_b : Whh_f;

    // load weight slice: wsm[k*32 + jloc] = Whh[(jloc>>3)*512 + gb*8 + (jloc&7)][k]
    for (int idx = tid; idx < 32 * (HH / 4); idx += 256) {
        int jloc = idx & 31;
        int kq = idx >> 5;  // 0..127
        int jg = (jloc >> 3) * HH + gb * 8 + (jloc & 7);
        float4 w = *(const float4*)(Whh + (size_t)jg * HH + kq * 4);
        wsm[(kq * 4 + 0) * 32 + jloc] = w.x;
        wsm[(kq * 4 + 1) * 32 + jloc] = w.y;
        wsm[(kq * 4 + 2) * 32 + jloc] = w.z;
        wsm[(kq * 4 + 3) * 32 + jloc] = w.w;
    }
    if (tid < 32) lsm[tid] = lens[tid];
    for (int idx = tid; idx < 8 * 33; idx += 256) csm[idx] = 0.f;
    __syncthreads();

    int tx = tid & 31;   // batch index for compute phase
    int ty = tid >> 5;   // 0..7 -> 4 gate rows jloc = ty*4..ty*4+3
    int j0 = (ty >> 1) * HH + gb * 8 + (ty & 1) * 4;  // global j of first row

    for (int s = 0; s < TT; s++) {
        int t = d ? (TT - 1 - s) : s;
        // prefetch x-projection (independent of h / barrier)
        float4 xp = *(const float4*)&g_xproj[d][t * BB + tx][j0];

        if (s > 0) {
            if (tid == 0) {
                unsigned int target = (unsigned int)(64 * s);
                while (atomicAdd(&g_bar[d], 0u) < target) __nanosleep(64);
            }
            __syncthreads();  // orders all threads after the observation
        }

        // stage h (phase s&1) into smem, L2-fresh via __ldcg
        int p = s & 1;
        const float4* hsrc = (const float4*)&g_h[p][d][0][0];
        for (int idx = tid; idx < (HH * BB) / 4; idx += 256) {
            float4 hv = __ldcg(hsrc + idx);
            int k = idx >> 3;
            int b = (idx & 7) * 4;
            float* dst = &hsm[k * 36 + b];
            dst[0] = hv.x; dst[1] = hv.y; dst[2] = hv.z; dst[3] = hv.w;
        }
        __syncthreads();

        // gates = xp + h @ Whh_slice^T   (f32x2 packed FMA)
        unsigned long long a01 = pk2(xp.x, xp.y);
        unsigned long long a23 = pk2(xp.z, xp.w);
#pragma unroll 8
        for (int k = 0; k < HH; k++) {
            float hv = hsm[k * 36 + tx];
            unsigned long long h2 = pk2(hv, hv);
            float4 w = *(const float4*)&wsm[k * 32 + ty * 4];
            a01 = fma2(pk2(w.x, w.y), h2, a01);
            a23 = fma2(pk2(w.z, w.w), h2, a23);
        }
        {
            float v0, v1, v2, v3;
            upk2(a01, v0, v1);
            upk2(a23, v2, v3);
            int jl = ty * 4;
            gsm[(jl + 0) * 33 + tx] = v0;
            gsm[(jl + 1) * 33 + tx] = v1;
            gsm[(jl + 2) * 33 + tx] = v2;
            gsm[(jl + 3) * 33 + tx] = v3;
        }
        __syncthreads();

        // elementwise LSTM cell for (b = tid&31, r = tid>>5)
        {
            int b = tid & 31, r = tid >> 5;
            float gi = gsm[(0 + r) * 33 + b];
            float gf = gsm[(8 + r) * 33 + b];
            float gg = gsm[(16 + r) * 33 + b];
            float go = gsm[(24 + r) * 33 + b];
            float i_ = 1.f / (1.f + expf(-gi));
            float f_ = 1.f / (1.f + expf(-gf));
            float g_ = tanhf(gg);
            float o_ = 1.f / (1.f + expf(-go));
            float c  = csm[r * 33 + b];
            float cn = f_ * c + i_ * g_;
            float hn = o_ * tanhf(cn);
            bool m = t < lsm[b];
            int kg = gb * 8 + r;
            float hold = hsm[kg * 36 + b];
            float hw = m ? hn : hold;
            if (m) csm[r * 33 + b] = cn;
            __stcg(&g_h[p ^ 1][d][kg][b], hw);   // coalesced across lanes (b)
            hbuf[r * 33 + b] = m ? hn : 0.f;
        }
        __threadfence();      // make h stores visible before arrival
        __syncthreads();
        if (tid == 0) atomicAdd(&g_bar[d], 1u);  // release arrival

        // write outputs (coalesced 32B runs over r)
        {
            int wid = tid >> 5, l = tid & 31;
            int b = wid * 4 + (l >> 3), r = l & 7;
            float v = hbuf[r * 33 + b];
            int kg = gb * 8 + r;
            out0[((size_t)(t * BB + b) * 2 + d) * HH + kg] = v;
            out1[((size_t)(d * TT + t) * BB + b) * HH + kg] = v;
        }
    }
}

// ================= launch =================
extern "C" void kernel_launch(void* const* d_in, const int* in_sizes, int n_in,
                              void* d_out, int out_size) {
    const int*   seq   = (const int*)d_in[0];
    const int*   lens  = (const int*)d_in[1];
    const float* emb   = (const float*)d_in[2];
    const float* Wih_f = (const float*)d_in[3];
    const float* Whh_f = (const float*)d_in[4];
    const float* bih_f = (const float*)d_in[5];
    const float* bhh_f = (const float*)d_in[6];
    const float* Wih_b = (const float*)d_in[7];
    const float* Whh_b = (const float*)d_in[8];
    const float* bih_b = (const float*)d_in[9];
    const float* bhh_b = (const float*)d_in[10];

    float* out  = (float*)d_out;
    float* out0 = out;                                   // outputs [T,B,2,H]
    float* out1 = out + (size_t)TT * BB * 2 * HH;        // hidden  [2,T,B,H]
    float* out2 = out1 + (size_t)2 * TT * BB * HH;       // embedded [T,B,H]

    // zero recurrent state + barrier counters (graph-capturable memsets)
    void* hptr; cudaGetSymbolAddress(&hptr, g_h);
    void* bptr; cudaGetSymbolAddress(&bptr, g_bar);
    cudaMemsetAsync(hptr, 0, sizeof(float) * 2 * 2 * HH * BB);
    cudaMemsetAsync(bptr, 0, sizeof(unsigned int) * 2);

    embed_kernel<<<TT * BB, 128>>>(seq, emb, out2);

    dim3 ggrid(G4 / 128, (TT * BB) / 128, 2);
    xproj_kernel<<<ggrid, 256>>>(out2, Wih_f, Wih_b, bih_f, bhh_f, bih_b, bhh_b);

    const int smem_bytes = (HH * 32 + HH * 36 + 32 * 33 + 8 * 33 + 8 * 33 + 32) * 4;
    cudaFuncSetAttribute(lstm_kernel, cudaFuncAttributeMaxDynamicSharedMemorySize, smem_bytes);
    lstm_kernel<<<128, 256, smem_bytes>>>(Whh_f, Whh_b, lens, out0, out1);
}